// round 10
// baseline (speedup 1.0000x reference)
#include <cuda_runtime.h>

// FeatureContraction: out[b,c,w,x,v] = sum_i x[b,c,w,x,v,i] * attr[b,c,i]
// x: [16384, 768, 16] f32, attr: [16384, 16] f32, out: [16384, 768] f32.
// Pure one-pass stream: 855 MB compulsory traffic.
//
// Session history:
// R1: float4 loads, 1 bc/CTA     -> 127.2 us @ 86% DRAM.
// R2: 8 bc/CTA SERIAL loop       -> 141.4 us (REGRESSION: dependency bubbles).
// R3: +ldcs/stcs hints           -> 127.0 us (NEUTRAL).
// R4: LDG.256 (v8.f32)           -> 124.8 us @ 87.6% DRAM, L1 71->43%.
// R5: hoist x loads over BAR     -> 124.8 us (kernel 122.3us; occ-invariant).
// R6: no smem/BAR, __ldg attr    -> 124.9 us (NEUTRAL).
// R7: 4 out/thr + STG.128        -> 133.6 us (REGRESSION: load batch serialized).
// R8: R5 confirmed               -> 124.77 us, 7009 GB/s == LTS floor.
// R9: PARALLEL 2-bc, 512 thr     -> 123.68 us (WIN: fewer CTAs, same shape).
// R10: PARALLEL 4-bc, 1024 thr, grid 4096 — same per-thread shape, CTA count
//      halved again. Occ ~33% (1 CTA/SM), proven non-binding.

#define BC_TOTAL   16384      // B*C
#define WXV        768        // X*Y*Y = 3*16*16
#define BC_PER_BLK 4
#define THREADS    (256 * BC_PER_BLK)       // 1024
#define PER_THR    3                         // outputs per thread
#define GRID       (BC_TOTAL / BC_PER_BLK)   // 4096

__device__ __forceinline__ void ldg256(const float* __restrict__ p,
                                       float4& lo, float4& hi)
{
    asm("ld.global.v8.f32 {%0,%1,%2,%3,%4,%5,%6,%7}, [%8];"
        : "=f"(lo.x), "=f"(lo.y), "=f"(lo.z), "=f"(lo.w),
          "=f"(hi.x), "=f"(hi.y), "=f"(hi.z), "=f"(hi.w)
        : "l"(p));
}

__global__ __launch_bounds__(THREADS)
void feature_contraction_kernel(const float* __restrict__ x,
                                const float4* __restrict__ attr,
                                float* __restrict__ out)
{
    // Each 256-thread sub-block handles one bc unit.
    const int sub  = threadIdx.x >> 8;          // 0..3
    const int tid  = threadIdx.x & 255;         // 0..255 within sub-block
    const int bc   = blockIdx.x * BC_PER_BLK + sub;

    const float* __restrict__ xb = x + (size_t)bc * WXV * 16;

    // ---- Phase 1: issue all 6 independent LDG.256 first. ----
    float4 v[PER_THR][4];
    int    o[PER_THR];

#pragma unroll
    for (int k = 0; k < PER_THR; k++) {
        o[k] = k * 256 + tid;
        const float* __restrict__ xp = xb + (size_t)o[k] * 16;
        ldg256(xp,     v[k][0], v[k][1]);
        ldg256(xp + 8, v[k][2], v[k][3]);
    }

    // ---- Phase 2: stage all 4 bc's attr vectors through smem, overlapped
    // with the x loads in flight. ----
    __shared__ float4 s_a[BC_PER_BLK][4];
    if (threadIdx.x < 4 * BC_PER_BLK) {
        const int j = threadIdx.x >> 2;          // which bc
        const int q = threadIdx.x & 3;           // which float4
        s_a[j][q] = attr[((size_t)blockIdx.x * BC_PER_BLK + j) * 4 + q];
    }
    __syncthreads();

    const float4 a0 = s_a[sub][0];
    const float4 a1 = s_a[sub][1];
    const float4 a2 = s_a[sub][2];
    const float4 a3 = s_a[sub][3];

    // ---- Phase 3: FMA + store. ----
#pragma unroll
    for (int k = 0; k < PER_THR; k++) {
        float s;
        s  = v[k][0].x * a0.x;
        s += v[k][0].y * a0.y;
        s += v[k][0].z * a0.z;
        s += v[k][0].w * a0.w;
        s += v[k][1].x * a1.x;
        s += v[k][1].y * a1.y;
        s += v[k][1].z * a1.z;
        s += v[k][1].w * a1.w;
        s += v[k][2].x * a2.x;
        s += v[k][2].y * a2.y;
        s += v[k][2].z * a2.z;
        s += v[k][2].w * a2.w;
        s += v[k][3].x * a3.x;
        s += v[k][3].y * a3.y;
        s += v[k][3].z * a3.z;
        s += v[k][3].w * a3.w;
        out[(size_t)bc * WXV + o[k]] = s;
    }
}

extern "C" void kernel_launch(void* const* d_in, const int* in_sizes, int n_in,
                              void* d_out, int out_size)
{
    const float*  x    = (const float*)d_in[0];
    const float4* attr = (const float4*)d_in[1];
    float*        out  = (float*)d_out;

    feature_contraction_kernel<<<GRID, THREADS>>>(x, attr, out);
}

// round 11
// speedup vs baseline: 1.0020x; 1.0020x over previous
#include <cuda_runtime.h>

// FeatureContraction: out[b,c,w,x,v] = sum_i x[b,c,w,x,v,i] * attr[b,c,i]
// x: [16384, 768, 16] f32, attr: [16384, 16] f32, out: [16384, 768] f32.
// Pure one-pass stream: 855 MB compulsory traffic.
//
// Session history:
// R1:  float4 loads, 1 bc/CTA    -> 127.2 us @ 86% DRAM.
// R2:  8 bc/CTA SERIAL loop      -> 141.4 us (REGRESSION: dependency bubbles).
// R3:  +ldcs/stcs hints          -> 127.0 us (NEUTRAL).
// R4:  LDG.256 (v8.f32)          -> 124.8 us @ 87.6% DRAM, L1 71->43%.
// R5:  hoist x loads over BAR    -> 124.8 us (kernel 122.3us; occ-invariant).
// R6:  no smem/BAR, __ldg attr   -> 124.9 us (NEUTRAL at 256 thr).
// R7:  4 out/thr + STG.128       -> 133.6 us (REGRESSION: load batch serialized).
// R8:  R5 confirmed              -> 124.77 us, 7009 GB/s == LTS floor.
// R9:  PARALLEL 2-bc, 512 thr    -> 123.68 us (WIN: fewer CTAs, same shape). BEST
// R10: PARALLEL 4-bc, 1024 thr   -> 125.66 us (REGRESSION: whole-SM barrier
//      coupling at 1 CTA/SM). CTA-width sweep: 256->124.8, 512->123.7(opt),
//      1024->125.7.
// R11: R9 structure, barrier-free — attr via uniform __ldg broadcast. Zero
//      inter-warp coupling; warps retire independently. FINAL.

#define BC_TOTAL   16384      // B*C
#define WXV        768        // X*Y*Y = 3*16*16
#define BC_PER_BLK 2
#define THREADS    (256 * BC_PER_BLK)       // 512
#define PER_THR    3                         // outputs per thread
#define GRID       (BC_TOTAL / BC_PER_BLK)   // 8192

__device__ __forceinline__ void ldg256(const float* __restrict__ p,
                                       float4& lo, float4& hi)
{
    asm("ld.global.v8.f32 {%0,%1,%2,%3,%4,%5,%6,%7}, [%8];"
        : "=f"(lo.x), "=f"(lo.y), "=f"(lo.z), "=f"(lo.w),
          "=f"(hi.x), "=f"(hi.y), "=f"(hi.z), "=f"(hi.w)
        : "l"(p));
}

__global__ __launch_bounds__(THREADS)
void feature_contraction_kernel(const float* __restrict__ x,
                                const float4* __restrict__ attr,
                                float* __restrict__ out)
{
    // Threads [0,256) handle bc0, threads [256,512) handle bc0+1.
    const int sub  = threadIdx.x >> 8;          // 0 or 1
    const int tid  = threadIdx.x & 255;         // 0..255 within sub-block
    const int bc   = blockIdx.x * BC_PER_BLK + sub;

    const float* __restrict__ xb = x + (size_t)bc * WXV * 16;

    // ---- Phase 1: issue all 6 independent LDG.256 first (true 48-reg
    // front-batch; nothing blocks them). ----
    float4 v[PER_THR][4];
    int    o[PER_THR];

#pragma unroll
    for (int k = 0; k < PER_THR; k++) {
        o[k] = k * 256 + tid;
        const float* __restrict__ xp = xb + (size_t)o[k] * 16;
        ldg256(xp,     v[k][0], v[k][1]);
        ldg256(xp + 8, v[k][2], v[k][3]);
    }

    // ---- Phase 2: attr[bc] via uniform-address broadcast loads — address
    // is warp-uniform (whole warp is in one sub-block), L1/L2 resident,
    // overlaps the x loads in flight. No smem, no barrier: zero inter-warp
    // coupling. ----
    const float4* __restrict__ ab = attr + (size_t)bc * 4;
    const float4 a0 = __ldg(ab + 0);
    const float4 a1 = __ldg(ab + 1);
    const float4 a2 = __ldg(ab + 2);
    const float4 a3 = __ldg(ab + 3);

    // ---- Phase 3: FMA + store. ----
#pragma unroll
    for (int k = 0; k < PER_THR; k++) {
        float s;
        s  = v[k][0].x * a0.x;
        s += v[k][0].y * a0.y;
        s += v[k][0].z * a0.z;
        s += v[k][0].w * a0.w;
        s += v[k][1].x * a1.x;
        s += v[k][1].y * a1.y;
        s += v[k][1].z * a1.z;
        s += v[k][1].w * a1.w;
        s += v[k][2].x * a2.x;
        s += v[k][2].y * a2.y;
        s += v[k][2].z * a2.z;
        s += v[k][2].w * a2.w;
        s += v[k][3].x * a3.x;
        s += v[k][3].y * a3.y;
        s += v[k][3].z * a3.z;
        s += v[k][3].w * a3.w;
        out[(size_t)bc * WXV + o[k]] = s;
    }
}

extern "C" void kernel_launch(void* const* d_in, const int* in_sizes, int n_in,
                              void* d_out, int out_size)
{
    const float*  x    = (const float*)d_in[0];
    const float4* attr = (const float4*)d_in[1];
    float*        out  = (float*)d_out;

    feature_contraction_kernel<<<GRID, THREADS>>>(x, attr, out);
}

// round 12
// speedup vs baseline: 1.0166x; 1.0145x over previous
#include <cuda_runtime.h>

// FeatureContraction: out[b,c,w,x,v] = sum_i x[b,c,w,x,v,i] * attr[b,c,i]
// x: [16384, 768, 16] f32, attr: [16384, 16] f32, out: [16384, 768] f32.
// Pure one-pass stream: 855 MB compulsory traffic. FINAL KERNEL (= R9).
//
// Session history:
// R1:  float4 loads, 1 bc/CTA    -> 127.2 us @ 86% DRAM.
// R2:  8 bc/CTA SERIAL loop      -> 141.4 us (REGRESSION: dependency bubbles).
// R3:  +ldcs/stcs hints          -> 127.0 us (NEUTRAL).
// R4:  LDG.256 (v8.f32)          -> 124.8 us @ 87.6% DRAM, L1 71->43%.
// R5:  hoist x loads over BAR    -> 124.8 us (kernel 122.3us; occ-invariant).
// R6:  no smem/BAR @256thr       -> 124.9 us (NEUTRAL).
// R7:  4 out/thr + STG.128       -> 133.6 us (REGRESSION: regs<needed, MLP lost).
// R8:  R5 confirmed              -> 124.77 us, 7009 GB/s == LTS floor.
// R9:  PARALLEL 2-bc, 512 thr    -> 123.68 us  ** BEST **
// R10: PARALLEL 4-bc, 1024 thr   -> 125.66 us (REGRESSION: whole-SM BAR coupling).
// R11: R9 minus smem/BAR         -> 125.41 us (REGRESSION: regs 62->40, ptxas
//      serialized the load front-batch; the BAR is what pins 48 load regs live).
//
// MODEL: time == 855 MB / ~7.0 TB/s (B300 path-independent LTS/DRAM cap)
// whenever the per-thread 6x LDG.256 front-batch survives regalloc. All other
// axes (occupancy 37-62%, cache hints, store width, barriers) are non-binding.

#define BC_TOTAL   16384      // B*C
#define WXV        768        // X*Y*Y = 3*16*16
#define BC_PER_BLK 2
#define THREADS    (256 * BC_PER_BLK)       // 512
#define PER_THR    3                         // outputs per thread
#define GRID       (BC_TOTAL / BC_PER_BLK)   // 8192

__device__ __forceinline__ void ldg256(const float* __restrict__ p,
                                       float4& lo, float4& hi)
{
    asm("ld.global.v8.f32 {%0,%1,%2,%3,%4,%5,%6,%7}, [%8];"
        : "=f"(lo.x), "=f"(lo.y), "=f"(lo.z), "=f"(lo.w),
          "=f"(hi.x), "=f"(hi.y), "=f"(hi.z), "=f"(hi.w)
        : "l"(p));
}

__global__ __launch_bounds__(THREADS)
void feature_contraction_kernel(const float* __restrict__ x,
                                const float4* __restrict__ attr,
                                float* __restrict__ out)
{
    // Threads [0,256) handle bc0, threads [256,512) handle bc0+1.
    const int sub  = threadIdx.x >> 8;          // 0 or 1
    const int tid  = threadIdx.x & 255;         // 0..255 within sub-block
    const int bc   = blockIdx.x * BC_PER_BLK + sub;

    const float* __restrict__ xb = x + (size_t)bc * WXV * 16;

    // ---- Phase 1: issue all 6 independent LDG.256 first (48-reg
    // front-batch; nothing blocks them). ----
    float4 v[PER_THR][4];
    int    o[PER_THR];

#pragma unroll
    for (int k = 0; k < PER_THR; k++) {
        o[k] = k * 256 + tid;
        const float* __restrict__ xp = xb + (size_t)o[k] * 16;
        ldg256(xp,     v[k][0], v[k][1]);
        ldg256(xp + 8, v[k][2], v[k][3]);
    }

    // ---- Phase 2: stage both bc's attr vectors through smem, overlapped
    // with the x loads in flight. The BAR here doubles as the scheduling
    // fence that keeps the 48 load-dest registers live (regs=62). ----
    __shared__ float4 s_a[BC_PER_BLK][4];
    if (threadIdx.x < 4 * BC_PER_BLK) {
        const int j = threadIdx.x >> 2;          // which bc
        const int q = threadIdx.x & 3;           // which float4
        s_a[j][q] = attr[((size_t)blockIdx.x * BC_PER_BLK + j) * 4 + q];
    }
    __syncthreads();

    const float4 a0 = s_a[sub][0];
    const float4 a1 = s_a[sub][1];
    const float4 a2 = s_a[sub][2];
    const float4 a3 = s_a[sub][3];

    // ---- Phase 3: FMA + store. ----
#pragma unroll
    for (int k = 0; k < PER_THR; k++) {
        float s;
        s  = v[k][0].x * a0.x;
        s += v[k][0].y * a0.y;
        s += v[k][0].z * a0.z;
        s += v[k][0].w * a0.w;
        s += v[k][1].x * a1.x;
        s += v[k][1].y * a1.y;
        s += v[k][1].z * a1.z;
        s += v[k][1].w * a1.w;
        s += v[k][2].x * a2.x;
        s += v[k][2].y * a2.y;
        s += v[k][2].z * a2.z;
        s += v[k][2].w * a2.w;
        s += v[k][3].x * a3.x;
        s += v[k][3].y * a3.y;
        s += v[k][3].z * a3.z;
        s += v[k][3].w * a3.w;
        out[(size_t)bc * WXV + o[k]] = s;
    }
}

extern "C" void kernel_launch(void* const* d_in, const int* in_sizes, int n_in,
                              void* d_out, int out_size)
{
    const float*  x    = (const float*)d_in[0];
    const float4* attr = (const float4*)d_in[1];
    float*        out  = (float*)d_out;

    feature_contraction_kernel<<<GRID, THREADS>>>(x, attr, out);
}

// round 13
// speedup vs baseline: 1.0184x; 1.0018x over previous
#include <cuda_runtime.h>

// FeatureContraction: out[b,c,w,x,v] = sum_i x[b,c,w,x,v,i] * attr[b,c,i]
// x: [16384, 768, 16] f32, attr: [16384, 16] f32, out: [16384, 768] f32.
// Pure one-pass stream: 855 MB compulsory traffic. FINAL KERNEL.
//
// Session history (12 rounds, single-variable experiments):
// R1:  float4 loads, 1 bc/CTA    -> 127.2 us @ 86% DRAM.
// R2:  8 bc/CTA SERIAL loop      -> 141.4 us (REGRESSION: dependency bubbles).
// R3:  +ldcs/stcs hints          -> 127.0 us (NEUTRAL).
// R4:  LDG.256 (v8.f32)          -> 124.8 us @ 87.6% DRAM, L1 71->43%.
// R5:  hoist x loads over BAR    -> 124.8 us (kernel 122.3us; occ-invariant).
// R6:  no smem/BAR @256thr       -> 124.9 us (NEUTRAL).
// R7:  4 out/thr + STG.128       -> 133.6 us (REGRESSION: regalloc killed MLP).
// R8:  R5 confirmed              -> 124.77 us, 7009 GB/s.
// R9:  PARALLEL 2-bc, 512 thr    -> 123.68 us (WIN).
// R10: PARALLEL 4-bc, 1024 thr   -> 125.66 us (REGRESSION: whole-SM BAR coupling).
// R11: R9 minus smem/BAR         -> 125.41 us (REGRESSION: regs 62->40, load
//      front-batch serialized; the BAR is the fence pinning 48 load regs live).
// R12: R9 reconfirmed            -> 123.62 us, kernel 121.57us, 7027 GB/s,
//      DRAM 88.7% @ occ 38%.  ** BEST — this kernel. **
//
// MODEL (validated by all 12 points): t == 855 MB / ~7.0 TB/s — the B300
// HBM/LTS streaming ceiling — iff the per-thread 6x LDG.256 front-batch
// survives register allocation (regs=62). Occupancy 37-62%, cache hints,
// store width, barrier presence, and CTA count 4k-16k are all non-binding.
// Remaining ~12% of HBM spec is DRAM read/write turnaround on a 16:1 mixed
// stream — not addressable from SASS (TMA == LDG path-independent cap).

#define BC_TOTAL   16384      // B*C
#define WXV        768        // X*Y*Y = 3*16*16
#define BC_PER_BLK 2
#define THREADS    (256 * BC_PER_BLK)       // 512
#define PER_THR    3                         // outputs per thread
#define GRID       (BC_TOTAL / BC_PER_BLK)   // 8192

__device__ __forceinline__ void ldg256(const float* __restrict__ p,
                                       float4& lo, float4& hi)
{
    asm("ld.global.v8.f32 {%0,%1,%2,%3,%4,%5,%6,%7}, [%8];"
        : "=f"(lo.x), "=f"(lo.y), "=f"(lo.z), "=f"(lo.w),
          "=f"(hi.x), "=f"(hi.y), "=f"(hi.z), "=f"(hi.w)
        : "l"(p));
}

__global__ __launch_bounds__(THREADS)
void feature_contraction_kernel(const float* __restrict__ x,
                                const float4* __restrict__ attr,
                                float* __restrict__ out)
{
    // Threads [0,256) handle bc0, threads [256,512) handle bc0+1.
    const int sub  = threadIdx.x >> 8;          // 0 or 1
    const int tid  = threadIdx.x & 255;         // 0..255 within sub-block
    const int bc   = blockIdx.x * BC_PER_BLK + sub;

    const float* __restrict__ xb = x + (size_t)bc * WXV * 16;

    // ---- Phase 1: issue all 6 independent LDG.256 first (48-reg
    // front-batch; nothing blocks them). ----
    float4 v[PER_THR][4];
    int    o[PER_THR];

#pragma unroll
    for (int k = 0; k < PER_THR; k++) {
        o[k] = k * 256 + tid;
        const float* __restrict__ xp = xb + (size_t)o[k] * 16;
        ldg256(xp,     v[k][0], v[k][1]);
        ldg256(xp + 8, v[k][2], v[k][3]);
    }

    // ---- Phase 2: stage both bc's attr vectors through smem, overlapped
    // with the x loads in flight. The BAR doubles as the scheduling fence
    // that keeps the 48 load-dest registers live (regs=62) — removing it
    // (R11) lets ptxas serialize the load batch and costs ~2 us. ----
    __shared__ float4 s_a[BC_PER_BLK][4];
    if (threadIdx.x < 4 * BC_PER_BLK) {
        const int j = threadIdx.x >> 2;          // which bc
        const int q = threadIdx.x & 3;           // which float4
        s_a[j][q] = attr[((size_t)blockIdx.x * BC_PER_BLK + j) * 4 + q];
    }
    __syncthreads();

    const float4 a0 = s_a[sub][0];
    const float4 a1 = s_a[sub][1];
    const float4 a2 = s_a[sub][2];
    const float4 a3 = s_a[sub][3];

    // ---- Phase 3: FMA + store. ----
#pragma unroll
    for (int k = 0; k < PER_THR; k++) {
        float s;
        s  = v[k][0].x * a0.x;
        s += v[k][0].y * a0.y;
        s += v[k][0].z * a0.z;
        s += v[k][0].w * a0.w;
        s += v[k][1].x * a1.x;
        s += v[k][1].y * a1.y;
        s += v[k][1].z * a1.z;
        s += v[k][1].w * a1.w;
        s += v[k][2].x * a2.x;
        s += v[k][2].y * a2.y;
        s += v[k][2].z * a2.z;
        s += v[k][2].w * a2.w;
        s += v[k][3].x * a3.x;
        s += v[k][3].y * a3.y;
        s += v[k][3].z * a3.z;
        s += v[k][3].w * a3.w;
        out[(size_t)bc * WXV + o[k]] = s;
    }
}

extern "C" void kernel_launch(void* const* d_in, const int* in_sizes, int n_in,
                              void* d_out, int out_size)
{
    const float*  x    = (const float*)d_in[0];
    const float4* attr = (const float4*)d_in[1];
    float*        out  = (float*)d_out;

    feature_contraction_kernel<<<GRID, THREADS>>>(x, attr, out);
}